// round 1
// baseline (speedup 1.0000x reference)
#include <cuda_runtime.h>

#define T_SEQ 4096
#define E_DIM 256
#define H_DIM 10
#define G_DIM 40
#define O_DIM 50257

// Scratch (allocation-free rule: __device__ globals)
__device__ float g_xg[T_SEQ * G_DIM];   // input-gate preactivations (incl. both biases)
__device__ float g_hs[T_SEQ * H_DIM];   // hidden states

typedef unsigned long long ull;

__device__ __forceinline__ ull pack2(float lo, float hi){
    ull r; asm("mov.b64 %0, {%1,%2};" : "=l"(r) : "f"(lo), "f"(hi)); return r;
}
__device__ __forceinline__ void unpack2(ull v, float& lo, float& hi){
    asm("mov.b64 {%0,%1}, %2;" : "=f"(lo), "=f"(hi) : "l"(v));
}
__device__ __forceinline__ ull fma2(ull a, ull b, ull c){
    ull d; asm("fma.rn.f32x2 %0, %1, %2, %3;" : "=l"(d) : "l"(a), "l"(b), "l"(c)); return d;
}
__device__ __forceinline__ ull add2(ull a, ull b){
    ull d; asm("add.rn.f32x2 %0, %1, %2;" : "=l"(d) : "l"(a), "l"(b)); return d;
}

// exp via EX2 (rel err ~1e-6), rcp via MUFU.RCP — accurate enough vs 1e-3 gate.
__device__ __forceinline__ float fexp(float x){
    float r; asm("ex2.approx.f32 %0, %1;" : "=f"(r) : "f"(x * 1.4426950408889634f)); return r;
}
__device__ __forceinline__ float frcp(float x){
    float r; asm("rcp.approx.f32 %0, %1;" : "=f"(r) : "f"(x)); return r;
}
__device__ __forceinline__ float fsig(float x){ return frcp(1.f + fexp(-x)); }
__device__ __forceinline__ float ftanh_(float x){ return 1.f - 2.f*frcp(1.f + fexp(2.f*x)); }
// large +x: fexp->inf -> rcp->0 -> 1 ; large -x: fexp->0 -> -1. Correct limits.

// ---------------------------------------------------------------------------
// Kernel A: xg[t][g] = emb[x[t]] . w_ih[g] + b_ih[g] + b_hh[g]
// 1 block per token, 4 warps, warp w owns gates [10w, 10w+10)
// ---------------------------------------------------------------------------
__global__ void xg_kernel(const int* __restrict__ x, const float* __restrict__ emb,
                          const float* __restrict__ w_ih, const float* __restrict__ b_ih,
                          const float* __restrict__ b_hh){
    __shared__ float4 e4[E_DIM/4];
    int t = blockIdx.x;
    int row = x[t];
    if (threadIdx.x < E_DIM/4)
        e4[threadIdx.x] = ((const float4*)(emb + (long long)row * E_DIM))[threadIdx.x];
    __syncthreads();
    int warp = threadIdx.x >> 5, lane = threadIdx.x & 31;
    #pragma unroll
    for (int gg = 0; gg < 10; gg++){
        int g = warp*10 + gg;
        const float4* w = (const float4*)(w_ih + g * E_DIM);
        float s = 0.f;
        #pragma unroll
        for (int i = lane; i < E_DIM/4; i += 32){
            float4 wv = w[i]; float4 ev = e4[i];
            s += wv.x*ev.x + wv.y*ev.y + wv.z*ev.z + wv.w*ev.w;
        }
        #pragma unroll
        for (int off = 16; off; off >>= 1) s += __shfl_xor_sync(0xffffffffu, s, off);
        if (lane == 0) g_xg[t*G_DIM + g] = s + b_ih[g] + b_hh[g];
    }
}

// ---------------------------------------------------------------------------
// Kernel B: serial LSTM scan. 1 warp. Lane j<10 owns hidden unit j; gates
// packed pairwise (i,f) and (g,o) into f32x2 accumulators. h broadcast by SHFL.
// xg prefetched one step ahead to hide L2 latency.
// ---------------------------------------------------------------------------
__global__ void scan_kernel(const float* __restrict__ w_hh){
    int lane = threadIdx.x & 31;
    int j = lane < H_DIM ? lane : H_DIM-1;   // clamp so idle lanes stay in-bounds

    ull wif[H_DIM], wgo[H_DIM];
    #pragma unroll
    for (int k = 0; k < H_DIM; k++){
        wif[k] = pack2(w_hh[(0*H_DIM + j)*H_DIM + k], w_hh[(1*H_DIM + j)*H_DIM + k]);
        wgo[k] = pack2(w_hh[(2*H_DIM + j)*H_DIM + k], w_hh[(3*H_DIM + j)*H_DIM + k]);
    }
    float hv[H_DIM];
    #pragma unroll
    for (int k = 0; k < H_DIM; k++) hv[k] = 0.f;
    float c = 0.f;

    const float* xg = g_xg;
    float xif0 = xg[j], xif1 = xg[H_DIM + j];
    float xgo0 = xg[2*H_DIM + j], xgo1 = xg[3*H_DIM + j];

    for (int t = 0; t < T_SEQ; t++){
        // prefetch next step (distance 1)
        int tn = (t+1 < T_SEQ) ? t+1 : t;
        const float* xr = xg + tn*G_DIM;
        float nif0 = xr[j], nif1 = xr[H_DIM + j];
        float ngo0 = xr[2*H_DIM + j], ngo1 = xr[3*H_DIM + j];

        // g = xg + W_hh h  — split accumulators to shorten FMA chain
        ull aifA = pack2(xif0, xif1), aifB = pack2(0.f, 0.f);
        ull agoA = pack2(xgo0, xgo1), agoB = pack2(0.f, 0.f);
        #pragma unroll
        for (int k = 0; k < H_DIM; k += 2){
            ull h0 = pack2(hv[k],   hv[k]);
            ull h1 = pack2(hv[k+1], hv[k+1]);
            aifA = fma2(h0, wif[k],   aifA);
            agoA = fma2(h0, wgo[k],   agoA);
            aifB = fma2(h1, wif[k+1], aifB);
            agoB = fma2(h1, wgo[k+1], agoB);
        }
        ull aif = add2(aifA, aifB), ago = add2(agoA, agoB);
        float gi, gf, gc, go;
        unpack2(aif, gi, gf); unpack2(ago, gc, go);

        float iv = fsig(gi), fv = fsig(gf), ov = fsig(go), tg = ftanh_(gc);
        c = fv*c + iv*tg;
        float h = ov * ftanh_(c);

        if (lane < H_DIM) g_hs[t*H_DIM + lane] = h;

        #pragma unroll
        for (int k = 0; k < H_DIM; k++) hv[k] = __shfl_sync(0xffffffffu, h, k);

        xif0 = nif0; xif1 = nif1; xgo0 = ngo0; xgo1 = ngo1;
    }
}

// ---------------------------------------------------------------------------
// Kernel C: logits[t][o] = hs[t] . W_out[o] + b_out[o]
// Block tile: 64 timesteps x 1024 outputs. 128 threads, 8 strided outputs each
// (o = base + q*128) -> every STG.32 is a fully-coalesced 128B line.
// h staged in smem pre-duplicated as f32x2 so inner loop is LDS.64 + fma2 only.
// ---------------------------------------------------------------------------
#define OT 1024
#define TT 64
#define NQ 8

__global__ __launch_bounds__(128) void out_kernel(const float* __restrict__ W,
                                                  const float* __restrict__ b,
                                                  float* __restrict__ out){
    __shared__ ull sh[TT * H_DIM];
    int tid = threadIdx.x;
    int bo = blockIdx.x, bt = blockIdx.y;

    for (int i = tid; i < TT*H_DIM; i += 128){
        float v = g_hs[bt*TT*H_DIM + i];
        sh[i] = pack2(v, v);
    }
    __syncthreads();

    int obase = bo*OT + tid;
    bool valid[NQ];
    #pragma unroll
    for (int q = 0; q < NQ; q++) valid[q] = (obase + q*128) < O_DIM;

    ull wp[NQ/2][H_DIM];
    ull bp[NQ/2];
    #pragma unroll
    for (int p = 0; p < NQ/2; p++){
        int o0 = obase + (2*p)*128, o1 = obase + (2*p+1)*128;
        float b0 = valid[2*p]   ? b[o0] : 0.f;
        float b1 = valid[2*p+1] ? b[o1] : 0.f;
        bp[p] = pack2(b0, b1);
        #pragma unroll
        for (int k = 0; k < H_DIM; k++){
            float w0 = valid[2*p]   ? W[o0*H_DIM + k] : 0.f;
            float w1 = valid[2*p+1] ? W[o1*H_DIM + k] : 0.f;
            wp[p][k] = pack2(w0, w1);
        }
    }

    #pragma unroll 2
    for (int tt = 0; tt < TT; tt++){
        ull acc[NQ/2];
        #pragma unroll
        for (int p = 0; p < NQ/2; p++) acc[p] = bp[p];
        #pragma unroll
        for (int k = 0; k < H_DIM; k++){
            ull hk = sh[tt*H_DIM + k];
            #pragma unroll
            for (int p = 0; p < NQ/2; p++) acc[p] = fma2(hk, wp[p][k], acc[p]);
        }
        long long rowoff = (long long)(bt*TT + tt) * O_DIM;
        #pragma unroll
        for (int p = 0; p < NQ/2; p++){
            float a0, a1; unpack2(acc[p], a0, a1);
            if (valid[2*p])   out[rowoff + obase + (2*p)*128]   = a0;
            if (valid[2*p+1]) out[rowoff + obase + (2*p+1)*128] = a1;
        }
    }
}

extern "C" void kernel_launch(void* const* d_in, const int* in_sizes, int n_in,
                              void* d_out, int out_size){
    const int*   x     = (const int*)  d_in[0];
    const float* emb   = (const float*)d_in[1];
    const float* w_ih  = (const float*)d_in[2];
    const float* w_hh  = (const float*)d_in[3];
    const float* b_ih  = (const float*)d_in[4];
    const float* b_hh  = (const float*)d_in[5];
    const float* W_out = (const float*)d_in[6];
    const float* b_out = (const float*)d_in[7];
    float* out = (float*)d_out;

    xg_kernel<<<T_SEQ, 128>>>(x, emb, w_ih, b_ih, b_hh);
    scan_kernel<<<1, 32>>>(w_hh);
    out_kernel<<<dim3((O_DIM + OT - 1)/OT, T_SEQ/TT), 128>>>(W_out, b_out, out);
}

// round 4
// speedup vs baseline: 2.6661x; 2.6661x over previous
#include <cuda_runtime.h>

#define T_SEQ 4096
#define E_DIM 256
#define H_DIM 10
#define G_DIM 40
#define O_DIM 50257
#define NBO   50          // ceil(O_DIM / OT)
#define OT    1024
#define TT    64
#define NQ    8
#define CHUNK 16

// Scratch (allocation-free rule: __device__ globals)
__device__ float g_xg[T_SEQ * G_DIM];   // input-gate preactivations (incl. both biases)
__device__ float g_hs[T_SEQ * H_DIM];   // hidden states
__device__ int   g_prog;                // scan progress (steps completed); zero-init

typedef unsigned long long ull;

__device__ __forceinline__ ull pack2(float lo, float hi){
    ull r; asm("mov.b64 %0, {%1,%2};" : "=l"(r) : "f"(lo), "f"(hi)); return r;
}
__device__ __forceinline__ void unpack2(ull v, float& lo, float& hi){
    asm("mov.b64 {%0,%1}, %2;" : "=f"(lo), "=f"(hi) : "l"(v));
}
__device__ __forceinline__ ull fma2(ull a, ull b, ull c){
    ull d; asm("fma.rn.f32x2 %0, %1, %2, %3;" : "=l"(d) : "l"(a), "l"(b), "l"(c)); return d;
}
__device__ __forceinline__ ull add2(ull a, ull b){
    ull d; asm("add.rn.f32x2 %0, %1, %2;" : "=l"(d) : "l"(a), "l"(b)); return d;
}

// MUFU tanh (sm_75+). Gate preactivations are small here (|x| <~ 1), where the
// approx error is far below the 1e-3 gate.
__device__ __forceinline__ float tanha(float x){
    float r; asm("tanh.approx.f32 %0, %1;" : "=f"(r) : "f"(x)); return r;
}
__device__ __forceinline__ float siga(float x){
    return fmaf(0.5f, tanha(0.5f*x), 0.5f);
}

// ---------------------------------------------------------------------------
// Kernel A: xg[t][g] = emb[x[t]] . w_ih[g] + b_ih[g] + b_hh[g]
// ---------------------------------------------------------------------------
__global__ void xg_kernel(const int* __restrict__ x, const float* __restrict__ emb,
                          const float* __restrict__ w_ih, const float* __restrict__ b_ih,
                          const float* __restrict__ b_hh){
    __shared__ float4 e4[E_DIM/4];
    int t = blockIdx.x;
    int row = x[t];
    if (threadIdx.x < E_DIM/4)
        e4[threadIdx.x] = ((const float4*)(emb + (long long)row * E_DIM))[threadIdx.x];
    __syncthreads();
    int warp = threadIdx.x >> 5, lane = threadIdx.x & 31;
    #pragma unroll
    for (int gg = 0; gg < 10; gg++){
        int g = warp*10 + gg;
        const float4* w = (const float4*)(w_ih + g * E_DIM);
        float s = 0.f;
        #pragma unroll
        for (int i = lane; i < E_DIM/4; i += 32){
            float4 wv = w[i]; float4 ev = e4[i];
            s += wv.x*ev.x + wv.y*ev.y + wv.z*ev.z + wv.w*ev.w;
        }
        #pragma unroll
        for (int off = 16; off; off >>= 1) s += __shfl_xor_sync(0xffffffffu, s, off);
        if (lane == 0) g_xg[t*G_DIM + g] = s + b_ih[g] + b_hh[g];
    }
}

// ---------------------------------------------------------------------------
// Fused kernel: block 0 warp 0 = serial LSTM scan (publishes progress);
// blocks 1..3200 = output GEMM tiles, spinning until their time chunk is done.
// ---------------------------------------------------------------------------
__global__ void __launch_bounds__(128) fused_kernel(const float* __restrict__ w_hh,
                                                    const float* __restrict__ W,
                                                    const float* __restrict__ b,
                                                    float* __restrict__ out){
    __shared__ float sxg[2*CHUNK*G_DIM];   // 32 steps of xg (double buffer), 5 KB
    __shared__ ull   sh[TT*H_DIM];         // h pairs for out tile, 5 KB

    if (blockIdx.x == 0){
        // ----------------- scan (warp 0 only) -----------------
        if (threadIdx.x >= 32) return;
        int lane = threadIdx.x;
        int j = lane < H_DIM ? lane : H_DIM-1;
        if (lane == 0) *((volatile int*)&g_prog) = 0;   // benign race across replays

        ull wif[H_DIM], wgo[H_DIM];
        #pragma unroll
        for (int k = 0; k < H_DIM; k++){
            wif[k] = pack2(w_hh[(0*H_DIM + j)*H_DIM + k], w_hh[(1*H_DIM + j)*H_DIM + k]);
            wgo[k] = pack2(w_hh[(2*H_DIM + j)*H_DIM + k], w_hh[(3*H_DIM + j)*H_DIM + k]);
        }
        float hv[H_DIM];
        #pragma unroll
        for (int k = 0; k < H_DIM; k++) hv[k] = 0.f;
        float c = 0.f;

        const float4* src = (const float4*)g_xg;   // 160 float4 per chunk
        // prologue: chunk 0 -> smem slot 0, chunk 1 -> regs
        float4 pre[5];
        #pragma unroll
        for (int r = 0; r < 5; r++) pre[r] = src[lane + 32*r];
        #pragma unroll
        for (int r = 0; r < 5; r++) ((float4*)sxg)[lane + 32*r] = pre[r];
        #pragma unroll
        for (int r = 0; r < 5; r++) pre[r] = src[160 + lane + 32*r];
        __syncwarp();

        float xif0 = sxg[j], xif1 = sxg[10+j], xgo0 = sxg[20+j], xgo1 = sxg[30+j];
        int t = 0;
        for (int chunk = 0; chunk < T_SEQ/CHUNK; chunk++){
            // stage chunk+1 into the other buffer; start LDG for chunk+2
            int p = (chunk+1) & 1;
            #pragma unroll
            for (int r = 0; r < 5; r++) ((float4*)sxg)[p*160 + lane + 32*r] = pre[r];
            int cn = chunk+2 < T_SEQ/CHUNK ? chunk+2 : T_SEQ/CHUNK-1;
            #pragma unroll
            for (int r = 0; r < 5; r++) pre[r] = src[cn*160 + lane + 32*r];
            __syncwarp();

            #pragma unroll 4
            for (int s = 0; s < CHUNK; s++, t++){
                // prefetch next step from smem (slot (t+1) mod 32)
                const float* nx = sxg + ((t+1)&31)*G_DIM;
                float nif0 = nx[j], nif1 = nx[10+j], ngo0 = nx[20+j], ngo1 = nx[30+j];

                ull aifA = pack2(xif0, xif1), aifB = pack2(0.f, 0.f);
                ull agoA = pack2(xgo0, xgo1), agoB = pack2(0.f, 0.f);
                #pragma unroll
                for (int k = 0; k < H_DIM; k += 2){
                    ull h0 = pack2(hv[k],   hv[k]);
                    ull h1 = pack2(hv[k+1], hv[k+1]);
                    aifA = fma2(h0, wif[k],   aifA);
                    agoA = fma2(h0, wgo[k],   agoA);
                    aifB = fma2(h1, wif[k+1], aifB);
                    agoB = fma2(h1, wgo[k+1], agoB);
                }
                ull aif = add2(aifA, aifB), ago = add2(agoA, agoB);
                float gi, gf, gc, go;
                unpack2(aif, gi, gf); unpack2(ago, gc, go);

                float iv = siga(gi), fv = siga(gf), ov = siga(go), tg = tanha(gc);
                c = fv*c + iv*tg;
                float h = ov * tanha(c);

                if (lane < H_DIM) g_hs[t*H_DIM + lane] = h;
                #pragma unroll
                for (int k = 0; k < H_DIM; k++) hv[k] = __shfl_sync(0xffffffffu, h, k);

                xif0 = nif0; xif1 = nif1; xgo0 = ngo0; xgo1 = ngo1;
            }
            // publish progress: t steps complete
            __threadfence();
            if (lane == 0) *((volatile int*)&g_prog) = t;
        }
        return;
    }

    // ----------------- output GEMM tile -----------------
    int bb = blockIdx.x - 1;
    int bo = bb % NBO;          // output-column tile (fastest-varying -> time-ordered waves)
    int bt = bb / NBO;          // time tile
    int tid = threadIdx.x;

    if (tid == 0){
        int need = (bt+1)*TT;
        while (*((volatile int*)&g_prog) < need) __nanosleep(256);
    }
    __syncthreads();
    __threadfence();            // order g_hs reads after observed flag

    for (int i = tid; i < TT*H_DIM; i += 128){
        float v = g_hs[bt*TT*H_DIM + i];
        sh[i] = pack2(v, v);
    }
    __syncthreads();

    int obase = bo*OT + tid;
    bool valid[NQ];
    #pragma unroll
    for (int q = 0; q < NQ; q++) valid[q] = (obase + q*128) < O_DIM;

    ull wp[NQ/2][H_DIM];
    ull bp[NQ/2];
    #pragma unroll
    for (int p = 0; p < NQ/2; p++){
        int o0 = obase + (2*p)*128, o1 = obase + (2*p+1)*128;
        float b0 = valid[2*p]   ? b[o0] : 0.f;
        float b1 = valid[2*p+1] ? b[o1] : 0.f;
        bp[p] = pack2(b0, b1);
        #pragma unroll
        for (int k = 0; k < H_DIM; k++){
            float w0 = valid[2*p]   ? W[o0*H_DIM + k] : 0.f;
            float w1 = valid[2*p+1] ? W[o1*H_DIM + k] : 0.f;
            wp[p][k] = pack2(w0, w1);
        }
    }

    #pragma unroll 2
    for (int tt = 0; tt < TT; tt++){
        ull acc[NQ/2];
        #pragma unroll
        for (int p = 0; p < NQ/2; p++) acc[p] = bp[p];
        #pragma unroll
        for (int k = 0; k < H_DIM; k++){
            ull hk = sh[tt*H_DIM + k];
            #pragma unroll
            for (int p = 0; p < NQ/2; p++) acc[p] = fma2(hk, wp[p][k], acc[p]);
        }
        long long rowoff = (long long)(bt*TT + tt) * O_DIM;
        #pragma unroll
        for (int p = 0; p < NQ/2; p++){
            float a0, a1; unpack2(acc[p], a0, a1);
            if (valid[2*p])   out[rowoff + obase + (2*p)*128]   = a0;
            if (valid[2*p+1]) out[rowoff + obase + (2*p+1)*128] = a1;
        }
    }
}

extern "C" void kernel_launch(void* const* d_in, const int* in_sizes, int n_in,
                              void* d_out, int out_size){
    const int*   x     = (const int*)  d_in[0];
    const float* emb   = (const float*)d_in[1];
    const float* w_ih  = (const float*)d_in[2];
    const float* w_hh  = (const float*)d_in[3];
    const float* b_ih  = (const float*)d_in[4];
    const float* b_hh  = (const float*)d_in[5];
    const float* W_out = (const float*)d_in[6];
    const float* b_out = (const float*)d_in[7];
    float* out = (float*)d_out;

    xg_kernel<<<T_SEQ, 128>>>(x, emb, w_ih, b_ih, b_hh);
    fused_kernel<<<1 + NBO*(T_SEQ/TT), 128>>>(w_hh, W_out, b_out, out);
}